// round 13
// baseline (speedup 1.0000x reference)
#include <cuda_runtime.h>
#include <cuda_fp16.h>
#include <cstdint>

#define B_    32
#define HW_   128
#define NPIX  16384
#define NIMG  2048

// 128MB scratch: f2 (tf32-rounded) transposed [b,c,w,h], then (f6+f2) in-place
__device__ float g_scratch[(size_t)B_ * 64 * NPIX];
// fp16-packed weight fragments: per thread-pattern t (128), 32 uint32:
// [ks 0..3][tile0 a0..a3, tile1 a0..a3]
__device__ uint32_t g_wtfh[4096];

// XOR-swizzled smem layout for fwht, stride 128 words (no pad)
__device__ __forceinline__ int sidx(int r, int h) {
    return r * 128 + ((((h >> 2) ^ r) & 31) << 2) + (h & 3);
}
__device__ __forceinline__ int sidx4(int r, int h4) {
    return r * 128 + (((h4 ^ r) & 31) << 2);
}

__device__ __forceinline__ uint32_t f2tf(float x) {
    uint32_t r; asm("cvt.rna.tf32.f32 %0, %1;" : "=r"(r) : "f"(x)); return r;
}
__device__ __forceinline__ float softth(float x, float t) {
    float tt = fmaxf(t, 0.f);
    return copysignf(fmaxf(fabsf(x) - tt, 0.f), x);
}
__device__ __forceinline__ uint32_t packh2(float lo, float hi) {
    __half2 h = __floats2half2_rn(lo, hi);
    return *(uint32_t*)&h;
}
__device__ __forceinline__ void mma_f16(float* d, uint32_t a0, uint32_t a1, uint32_t a2, uint32_t a3,
                                        uint32_t b0, uint32_t b1) {
    asm volatile(
        "mma.sync.aligned.m16n8k16.row.col.f32.f16.f16.f32 "
        "{%0,%1,%2,%3}, {%4,%5,%6,%7}, {%8,%9}, {%0,%1,%2,%3};\n"
        : "+f"(d[0]), "+f"(d[1]), "+f"(d[2]), "+f"(d[3])
        : "r"(a0), "r"(a1), "r"(a2), "r"(a3), "r"(b0), "r"(b1));
}

// ---------------------------------------------------------------------------
// prep: conv_w -> fp16 fragment-packed for m16n8k16 mainloop.
// ---------------------------------------------------------------------------
__global__ void prep_kernel(const float* __restrict__ W)
{
    int t = threadIdx.x;                 // 128 threads
    int tig = t & 3, gid = (t >> 2) & 7, mq = t >> 5;
    int o = mq * 16 + gid;
    #pragma unroll
    for (int ks = 0; ks < 4; ks++) {
        int k0 = ks * 16 + 2 * tig;
        uint32_t* out = g_wtfh + t * 32 + ks * 8;
        #pragma unroll
        for (int pod = 0; pod < 2; pod++) {
            const float* Wp = W + pod * 4096;
            out[pod*4 + 0] = packh2(__ldg(Wp + o*64 + k0),         __ldg(Wp + o*64 + k0 + 1));
            out[pod*4 + 1] = packh2(__ldg(Wp + (o+8)*64 + k0),     __ldg(Wp + (o+8)*64 + k0 + 1));
            out[pod*4 + 2] = packh2(__ldg(Wp + o*64 + k0 + 8),     __ldg(Wp + o*64 + k0 + 9));
            out[pod*4 + 3] = packh2(__ldg(Wp + (o+8)*64 + k0 + 8), __ldg(Wp + (o+8)*64 + k0 + 9));
        }
    }
}

// ---------------------------------------------------------------------------
// Pass 1 / Pass 3: 2D FWHT of 128x128 image, output TRANSPOSED, scaled.
// (Exact R5-proven structure, frozen.)
// ---------------------------------------------------------------------------
__global__ void __launch_bounds__(256, 2)
fwht2d_kernel(const float* __restrict__ in, float* __restrict__ out,
              float scale, int do_round)
{
    extern __shared__ float s[];
    const int img = blockIdx.x;
    const int tid = threadIdx.x;
    const float* gin  = in  + (size_t)img * NPIX;
    float*       gout = out + (size_t)img * NPIX;

    #pragma unroll
    for (int k = 0; k < 16; k++) {
        int gi = k * 256 + tid;
        int r  = gi >> 5;
        int c4 = gi & 31;
        float4 v4 = __ldg((const float4*)gin + gi);
        *(float4*)&s[sidx4(r, c4)] = v4;
    }
    __syncthreads();

    float reg[64];

    // phase W
    {
        int r = tid >> 1, half = tid & 1;
        #pragma unroll
        for (int j4 = 0; j4 < 16; j4++) {
            float4 a = *(const float4*)&s[sidx4(r, j4)];
            float4 b = *(const float4*)&s[sidx4(r, j4 + 16)];
            if (half) {
                reg[4*j4+0] = a.x - b.x; reg[4*j4+1] = a.y - b.y;
                reg[4*j4+2] = a.z - b.z; reg[4*j4+3] = a.w - b.w;
            } else {
                reg[4*j4+0] = a.x + b.x; reg[4*j4+1] = a.y + b.y;
                reg[4*j4+2] = a.z + b.z; reg[4*j4+3] = a.w + b.w;
            }
        }
        #pragma unroll
        for (int st = 1; st < 64; st <<= 1)
            #pragma unroll
            for (int i = 0; i < 64; i++)
                if ((i & st) == 0) {
                    float a = reg[i], b = reg[i + st];
                    reg[i] = a + b;  reg[i + st] = a - b;
                }
        __syncthreads();
        #pragma unroll
        for (int j4 = 0; j4 < 16; j4++)
            *(float4*)&s[sidx4(r, half * 16 + j4)] =
                make_float4(reg[4*j4], reg[4*j4+1], reg[4*j4+2], reg[4*j4+3]);
    }
    __syncthreads();

    // phase H (writes transposed)
    {
        int w = tid & 127, hh = tid >> 7;
        #pragma unroll
        for (int j = 0; j < 64; j++) {
            float a = s[sidx(j, w)];
            float b = s[sidx(j + 64, w)];
            reg[j] = hh ? (a - b) : (a + b);
        }
        #pragma unroll
        for (int st = 1; st < 64; st <<= 1)
            #pragma unroll
            for (int i = 0; i < 64; i++)
                if ((i & st) == 0) {
                    float a = reg[i], b = reg[i + st];
                    reg[i] = a + b;  reg[i + st] = a - b;
                }
        __syncthreads();
        #pragma unroll
        for (int j4 = 0; j4 < 16; j4++)
            *(float4*)&s[sidx4(w, hh * 16 + j4)] =
                make_float4(reg[4*j4], reg[4*j4+1], reg[4*j4+2], reg[4*j4+3]);
    }
    __syncthreads();

    if (do_round) {
        #pragma unroll
        for (int k = 0; k < 16; k++) {
            int gi = k * 256 + tid;
            int r  = gi >> 5;
            int c4 = gi & 31;
            float4 t = *(const float4*)&s[sidx4(r, c4)];
            ((float4*)gout)[gi] = make_float4(
                __uint_as_float(f2tf(t.x)), __uint_as_float(f2tf(t.y)),
                __uint_as_float(f2tf(t.z)), __uint_as_float(f2tf(t.w)));
        }
    } else {
        #pragma unroll
        for (int k = 0; k < 16; k++) {
            int gi = k * 256 + tid;
            int r  = gi >> 5;
            int c4 = gi & 31;
            float4 t = *(const float4*)&s[sidx4(r, c4)];
            ((float4*)gout)[gi] = make_float4(t.x*scale, t.y*scale, t.z*scale, t.w*scale);
        }
    }
}

// ---------------------------------------------------------------------------
// Pass 2: fp16 mma.sync (m16n8k16) per (b,w) tile. R5 chassis:
// stage fp32 tile -> pack half2 [c/2][h] -> 64 MMA/warp -> R5 epilogue/store.
// smem: Bsf[64][136] fp32 (8704) + Bs2[32][136] u32 (4352) + vt (512) = 54272B
// ---------------------------------------------------------------------------
__global__ void __launch_bounds__(256, 2)
podmix_kernel(float* __restrict__ f2, const float* __restrict__ v,
              const float* __restrict__ T)
{
    extern __shared__ float sm[];
    float*    Bsf  = sm;                       // fp32 tile [64][136]
    uint32_t* Bs2u = (uint32_t*)(sm + 8704);   // half2 tile [32 c2][136 h]
    float*    vs0  = sm + 8704 + 4352;
    float*    Ts0  = vs0 + 128;
    float*    vs1  = Ts0 + 128;
    float*    Ts1  = vs1 + 128;

    const int b    = blockIdx.x >> 7;
    const int w    = blockIdx.x & 127;
    const int tid  = threadIdx.x;
    const int wid  = tid >> 5;
    const int lane = tid & 31;
    const int gid  = lane >> 2;   // 0..7
    const int tig  = lane & 3;    // 0..3
    const int mq   = wid & 3;     // o-quarter (16 rows x 2 pods)
    const int nh   = wid >> 2;    // h half

    float* gtile = f2 + (((size_t)b * 64) * 128 + w) * 128;   // + c*NPIX + h

    // stage f2 tile (tf32-rounded fp32) -> Bsf
    #pragma unroll
    for (int k = 0; k < 8; k++) {
        int i4 = k * 256 + tid;          // 2048 float4
        int c  = i4 >> 5;
        int h4 = i4 & 31;
        float4 t = __ldg((const float4*)(gtile + (size_t)c * NPIX) + h4);
        *(float4*)&Bsf[c * 136 + h4 * 4] = t;
    }
    // v/T columns for this w
    if (tid < 128) {
        vs0[tid] = __ldg(v + tid * 128 + w);
        Ts0[tid] = __ldg(T + tid * 128 + w);
    } else {
        int h = tid - 128;
        vs1[h] = __ldg(v + NPIX + h * 128 + w);
        Ts1[h] = __ldg(T + NPIX + h * 128 + w);
    }
    __syncthreads();

    // pack fp32 -> half2 along c: Bs2[c2][h] = (f2[2c2][h], f2[2c2+1][h])
    // 32 c2-rows x 128 h = 4096 entries
    #pragma unroll
    for (int k = 0; k < 16; k++) {
        int e  = k * 256 + tid;
        int c2 = e >> 7;                 // 0..31
        int hh = e & 127;
        Bs2u[c2 * 136 + hh] = packh2(Bsf[(2*c2) * 136 + hh], Bsf[(2*c2+1) * 136 + hh]);
    }
    __syncthreads();

    float acc[16][4];
    #pragma unroll
    for (int i = 0; i < 16; i++) {
        acc[i][0] = 0.f; acc[i][1] = 0.f; acc[i][2] = 0.f; acc[i][3] = 0.f;
    }

    const uint4* Ap = (const uint4*)(g_wtfh + (mq * 32 + gid * 4 + tig) * 32);

    #pragma unroll
    for (int ks = 0; ks < 4; ks++) {
        uint4 q0 = __ldg(Ap + ks * 2);       // tile0 a0..a3 (pod0)
        uint4 q1 = __ldg(Ap + ks * 2 + 1);   // tile1 a0..a3 (pod1)
        int r0 = (ks * 8 + tig) * 136 + nh * 64 + gid;
        int r1 = r0 + 4 * 136;
        #pragma unroll
        for (int nb = 0; nb < 8; nb++) {
            uint32_t b0 = Bs2u[r0 + nb * 8];
            uint32_t b1 = Bs2u[r1 + nb * 8];
            mma_f16(acc[nb],     q0.x, q0.y, q0.z, q0.w, b0, b1);   // pod 0
            mma_f16(acc[8 + nb], q1.x, q1.y, q1.z, q1.w, b0, b1);   // pod 1
        }
    }
    // no sync needed: GEMM reads Bs2u, epilogue reads/writes only its own
    // thread's Bsf cells (disjoint regions / same-thread ordering)

    // epilogue: combine pods in registers, add f2, write into Bsf
    {
        const int o = mq * 16 + gid;
        #pragma unroll
        for (int nb = 0; nb < 8; nb++) {
            int h = nh * 64 + nb * 8 + 2 * tig;
            float v0h = vs0[h], v0h1 = vs0[h+1], t0h = Ts0[h], t0h1 = Ts0[h+1];
            float v1h = vs1[h], v1h1 = vs1[h+1], t1h = Ts1[h], t1h1 = Ts1[h+1];
            float2 f0 = *(const float2*)&Bsf[o * 136 + h];
            float2 f1 = *(const float2*)&Bsf[(o + 8) * 136 + h];
            float2 r0 = make_float2(
                softth(v0h  * acc[nb][0], t0h)  + softth(v1h  * acc[8+nb][0], t1h)  + f0.x,
                softth(v0h1 * acc[nb][1], t0h1) + softth(v1h1 * acc[8+nb][1], t1h1) + f0.y);
            float2 r1 = make_float2(
                softth(v0h  * acc[nb][2], t0h)  + softth(v1h  * acc[8+nb][2], t1h)  + f1.x,
                softth(v0h1 * acc[nb][3], t0h1) + softth(v1h1 * acc[8+nb][3], t1h1) + f1.y);
            *(float2*)&Bsf[o * 136 + h]       = r0;
            *(float2*)&Bsf[(o + 8) * 136 + h] = r1;
        }
    }
    __syncthreads();

    // coalesced store back in place
    #pragma unroll
    for (int k = 0; k < 8; k++) {
        int i4 = k * 256 + tid;
        int c  = i4 >> 5;
        int h4 = i4 & 31;
        float4 t = *(const float4*)&Bsf[c * 136 + h4 * 4];
        *((float4*)(gtile + (size_t)c * NPIX) + h4) = t;
    }
}

extern "C" void kernel_launch(void* const* d_in, const int* in_sizes, int n_in,
                              void* d_out, int out_size)
{
    (void)in_sizes; (void)n_in; (void)out_size;
    const float* x = (const float*)d_in[0];
    const float* v = (const float*)d_in[1];
    const float* T = (const float*)d_in[2];
    const float* W = (const float*)d_in[3];
    float* out = (float*)d_out;

    float* scratch = nullptr;
    cudaGetSymbolAddress((void**)&scratch, g_scratch);

    const int smem1 = 128 * 128 * 4;                   // 65536 B
    const int smem2 = (8704 + 4352 + 512) * 4;         // 54272 B
    cudaFuncSetAttribute(fwht2d_kernel, cudaFuncAttributeMaxDynamicSharedMemorySize, smem1);
    cudaFuncSetAttribute(podmix_kernel, cudaFuncAttributeMaxDynamicSharedMemorySize, smem2);

    prep_kernel<<<1, 128>>>(W);
    fwht2d_kernel<<<NIMG, 256, smem1>>>(x, scratch, 1.0f, 1);
    podmix_kernel<<<B_ * 128, 256, smem2>>>(scratch, v, T);
    fwht2d_kernel<<<NIMG, 256, smem1>>>(scratch, out, 1.0f / 16384.0f, 0);
}

// round 14
// speedup vs baseline: 1.1131x; 1.1131x over previous
#include <cuda_runtime.h>
#include <cstdint>

#define B_    32
#define HW_   128
#define NPIX  16384
#define NIMG  2048

// 128MB scratch: f2 (tf32-rounded) transposed [b,c,w,h], then (f6+f2) in-place
__device__ float g_scratch[(size_t)B_ * 64 * NPIX];
// pre-converted tf32 weights in per-thread fragment order
__device__ float g_wtf[8192];

// XOR-swizzled smem layout for fwht, stride 128 words (no pad)
__device__ __forceinline__ int sidx(int r, int h) {
    return r * 128 + ((((h >> 2) ^ r) & 31) << 2) + (h & 3);
}
__device__ __forceinline__ int sidx4(int r, int h4) {
    return r * 128 + (((h4 ^ r) & 31) << 2);
}

__device__ __forceinline__ uint32_t f2tf(float x) {
    uint32_t r; asm("cvt.rna.tf32.f32 %0, %1;" : "=r"(r) : "f"(x)); return r;
}
__device__ __forceinline__ float softth(float x, float t) {
    float tt = fmaxf(t, 0.f);
    return copysignf(fmaxf(fabsf(x) - tt, 0.f), x);
}
__device__ __forceinline__ void mma_tf32(float* d, uint32_t a0, uint32_t a1, uint32_t a2, uint32_t a3,
                                         uint32_t b0, uint32_t b1) {
    asm volatile(
        "mma.sync.aligned.m16n8k8.row.col.f32.tf32.tf32.f32 "
        "{%0,%1,%2,%3}, {%4,%5,%6,%7}, {%8,%9}, {%0,%1,%2,%3};\n"
        : "+f"(d[0]), "+f"(d[1]), "+f"(d[2]), "+f"(d[3])
        : "r"(a0), "r"(a1), "r"(a2), "r"(a3), "r"(b0), "r"(b1));
}
__device__ __forceinline__ void cpa16(uint32_t d, const void* s) {
    asm volatile("cp.async.cg.shared.global [%0], [%1], 16;" :: "r"(d), "l"(s));
}
__device__ __forceinline__ void cpa_commit_wait() {
    asm volatile("cp.async.commit_group;" ::: "memory");
    asm volatile("cp.async.wait_group 0;" ::: "memory");
}

// ---------------------------------------------------------------------------
// prep: conv_w -> tf32, fragment-ordered for podmix mainloop
// ---------------------------------------------------------------------------
__global__ void prep_kernel(const float* __restrict__ W)
{
    int t = blockIdx.x * 256 + threadIdx.x;
    if (t >= 1024) return;
    int tig = t & 3, gid = (t >> 2) & 7, mq = (t >> 5) & 3, kb = t >> 7;
    int k0 = kb * 8 + tig;
    int r0 = mq * 16 + gid;
    float* o = g_wtf + t * 8;
    o[0] = __uint_as_float(f2tf(__ldg(W + r0 * 64 + k0)));
    o[1] = __uint_as_float(f2tf(__ldg(W + (r0 + 8) * 64 + k0)));
    o[2] = __uint_as_float(f2tf(__ldg(W + r0 * 64 + k0 + 4)));
    o[3] = __uint_as_float(f2tf(__ldg(W + (r0 + 8) * 64 + k0 + 4)));
    int r1 = r0 + 64;
    o[4] = __uint_as_float(f2tf(__ldg(W + r1 * 64 + k0)));
    o[5] = __uint_as_float(f2tf(__ldg(W + (r1 + 8) * 64 + k0)));
    o[6] = __uint_as_float(f2tf(__ldg(W + r1 * 64 + k0 + 4)));
    o[7] = __uint_as_float(f2tf(__ldg(W + (r1 + 8) * 64 + k0 + 4)));
}

// ---------------------------------------------------------------------------
// Pass 1 / Pass 3: 2D FWHT of 128x128 image, output TRANSPOSED, scaled.
// (R5-proven structure; stage-in now via cp.async — pure copy, same layout.)
// ---------------------------------------------------------------------------
__global__ void __launch_bounds__(256, 2)
fwht2d_kernel(const float* __restrict__ in, float* __restrict__ out,
              float scale, int do_round)
{
    extern __shared__ float s[];
    const int img = blockIdx.x;
    const int tid = threadIdx.x;
    const float* gin  = in  + (size_t)img * NPIX;
    float*       gout = out + (size_t)img * NPIX;

    // stage in: gmem -> swizzled smem via cp.async (no register round-trip)
    {
        uint32_t sdst = (uint32_t)__cvta_generic_to_shared(s);
        #pragma unroll
        for (int k = 0; k < 16; k++) {
            int gi = k * 256 + tid;          // float4 index, 4096 total
            int r  = gi >> 5;
            int c4 = gi & 31;
            cpa16(sdst + sidx4(r, c4) * 4, (const float4*)gin + gi);
        }
        cpa_commit_wait();
    }
    __syncthreads();

    float reg[64];

    // phase W
    {
        int r = tid >> 1, half = tid & 1;
        #pragma unroll
        for (int j4 = 0; j4 < 16; j4++) {
            float4 a = *(const float4*)&s[sidx4(r, j4)];
            float4 b = *(const float4*)&s[sidx4(r, j4 + 16)];
            if (half) {
                reg[4*j4+0] = a.x - b.x; reg[4*j4+1] = a.y - b.y;
                reg[4*j4+2] = a.z - b.z; reg[4*j4+3] = a.w - b.w;
            } else {
                reg[4*j4+0] = a.x + b.x; reg[4*j4+1] = a.y + b.y;
                reg[4*j4+2] = a.z + b.z; reg[4*j4+3] = a.w + b.w;
            }
        }
        #pragma unroll
        for (int st = 1; st < 64; st <<= 1)
            #pragma unroll
            for (int i = 0; i < 64; i++)
                if ((i & st) == 0) {
                    float a = reg[i], b = reg[i + st];
                    reg[i] = a + b;  reg[i + st] = a - b;
                }
        __syncthreads();
        #pragma unroll
        for (int j4 = 0; j4 < 16; j4++)
            *(float4*)&s[sidx4(r, half * 16 + j4)] =
                make_float4(reg[4*j4], reg[4*j4+1], reg[4*j4+2], reg[4*j4+3]);
    }
    __syncthreads();

    // phase H (writes transposed)
    {
        int w = tid & 127, hh = tid >> 7;
        #pragma unroll
        for (int j = 0; j < 64; j++) {
            float a = s[sidx(j, w)];
            float b = s[sidx(j + 64, w)];
            reg[j] = hh ? (a - b) : (a + b);
        }
        #pragma unroll
        for (int st = 1; st < 64; st <<= 1)
            #pragma unroll
            for (int i = 0; i < 64; i++)
                if ((i & st) == 0) {
                    float a = reg[i], b = reg[i + st];
                    reg[i] = a + b;  reg[i + st] = a - b;
                }
        __syncthreads();
        #pragma unroll
        for (int j4 = 0; j4 < 16; j4++)
            *(float4*)&s[sidx4(w, hh * 16 + j4)] =
                make_float4(reg[4*j4], reg[4*j4+1], reg[4*j4+2], reg[4*j4+3]);
    }
    __syncthreads();

    if (do_round) {
        #pragma unroll
        for (int k = 0; k < 16; k++) {
            int gi = k * 256 + tid;
            int r  = gi >> 5;
            int c4 = gi & 31;
            float4 t = *(const float4*)&s[sidx4(r, c4)];
            ((float4*)gout)[gi] = make_float4(
                __uint_as_float(f2tf(t.x)), __uint_as_float(f2tf(t.y)),
                __uint_as_float(f2tf(t.z)), __uint_as_float(f2tf(t.w)));
        }
    } else {
        #pragma unroll
        for (int k = 0; k < 16; k++) {
            int gi = k * 256 + tid;
            int r  = gi >> 5;
            int c4 = gi & 31;
            float4 t = *(const float4*)&s[sidx4(r, c4)];
            ((float4*)gout)[gi] = make_float4(t.x*scale, t.y*scale, t.z*scale, t.w*scale);
        }
    }
}

// ---------------------------------------------------------------------------
// Pass 2: mma.sync tf32 per (b,w) tile (R5-proven structure;
// B-tile staging via cp.async).
// ---------------------------------------------------------------------------
__global__ void __launch_bounds__(256, 2)
podmix_kernel(float* __restrict__ f2, const float* __restrict__ v,
              const float* __restrict__ T)
{
    __shared__ float sm[9216];
    float*    Bs  = sm;               // [64 c][136 h] tf32 bits of f2 tile
    uint32_t* Bsu = (uint32_t*)sm;
    float*    vs0 = sm + 8704;
    float*    Ts0 = vs0 + 128;
    float*    vs1 = Ts0 + 128;
    float*    Ts1 = vs1 + 128;

    const int b    = blockIdx.x >> 7;
    const int w    = blockIdx.x & 127;
    const int tid  = threadIdx.x;
    const int wid  = tid >> 5;
    const int lane = tid & 31;
    const int gid  = lane >> 2;   // 0..7
    const int tig  = lane & 3;    // 0..3
    const int mq   = wid & 3;     // o-quarter (16 rows)
    const int nh   = wid >> 2;    // h half

    float* gtile = f2 + (((size_t)b * 64) * 128 + w) * 128;   // + c*NPIX + h

    // stage f2 tile (already tf32 bits) -> Bs via cp.async (pure copy)
    {
        uint32_t bsd = (uint32_t)__cvta_generic_to_shared(Bs);
        #pragma unroll
        for (int k = 0; k < 8; k++) {
            int i4 = k * 256 + tid;          // 2048 float4
            int c  = i4 >> 5;
            int h4 = i4 & 31;
            cpa16(bsd + (c * 136 + h4 * 4) * 4,
                  (const float4*)(gtile + (size_t)c * NPIX) + h4);
        }
    }
    // v/T columns for this w (regular loads, tiny)
    if (tid < 128) {
        vs0[tid] = __ldg(v + tid * 128 + w);
        Ts0[tid] = __ldg(T + tid * 128 + w);
    } else {
        int h = tid - 128;
        vs1[h] = __ldg(v + NPIX + h * 128 + w);
        Ts1[h] = __ldg(T + NPIX + h * 128 + w);
    }
    cpa_commit_wait();
    __syncthreads();

    float acc[16][4];
    #pragma unroll
    for (int i = 0; i < 16; i++) {
        acc[i][0] = 0.f; acc[i][1] = 0.f; acc[i][2] = 0.f; acc[i][3] = 0.f;
    }

    const float4* Aw = (const float4*)g_wtf;

    #pragma unroll
    for (int kb = 0; kb < 8; kb++) {
        int ai = (((kb * 4 + mq) * 8 + gid) * 4 + tig) * 2;
        float4 lo = __ldg(Aw + ai);
        float4 hi = __ldg(Aw + ai + 1);
        uint32_t a0 = __float_as_uint(lo.x), a1 = __float_as_uint(lo.y);
        uint32_t a2 = __float_as_uint(lo.z), a3 = __float_as_uint(lo.w);
        uint32_t a4 = __float_as_uint(hi.x), a5 = __float_as_uint(hi.y);
        uint32_t a6 = __float_as_uint(hi.z), a7 = __float_as_uint(hi.w);
        int r0 = (kb * 8 + tig) * 136 + nh * 64 + gid;
        int r1 = r0 + 4 * 136;
        #pragma unroll
        for (int nb = 0; nb < 8; nb++) {
            uint32_t b0 = Bsu[r0 + nb * 8];
            uint32_t b1 = Bsu[r1 + nb * 8];
            mma_tf32(acc[nb],     a0, a1, a2, a3, b0, b1);   // pod 0
            mma_tf32(acc[8 + nb], a4, a5, a6, a7, b0, b1);   // pod 1
        }
    }
    __syncthreads();   // all GEMM reads of Bs done

    // epilogue: combine pods in registers, add f2, write back into Bs
    {
        const int o = mq * 16 + gid;
        #pragma unroll
        for (int nb = 0; nb < 8; nb++) {
            int h = nh * 64 + nb * 8 + 2 * tig;
            float v0h = vs0[h], v0h1 = vs0[h+1], t0h = Ts0[h], t0h1 = Ts0[h+1];
            float v1h = vs1[h], v1h1 = vs1[h+1], t1h = Ts1[h], t1h1 = Ts1[h+1];
            float2 f0 = *(const float2*)&Bs[o * 136 + h];
            float2 f1 = *(const float2*)&Bs[(o + 8) * 136 + h];
            float2 r0 = make_float2(
                softth(v0h  * acc[nb][0], t0h)  + softth(v1h  * acc[8+nb][0], t1h)  + f0.x,
                softth(v0h1 * acc[nb][1], t0h1) + softth(v1h1 * acc[8+nb][1], t1h1) + f0.y);
            float2 r1 = make_float2(
                softth(v0h  * acc[nb][2], t0h)  + softth(v1h  * acc[8+nb][2], t1h)  + f1.x,
                softth(v0h1 * acc[nb][3], t0h1) + softth(v1h1 * acc[8+nb][3], t1h1) + f1.y);
            *(float2*)&Bs[o * 136 + h]       = r0;
            *(float2*)&Bs[(o + 8) * 136 + h] = r1;
        }
    }
    __syncthreads();

    // coalesced store back in place
    #pragma unroll
    for (int k = 0; k < 8; k++) {
        int i4 = k * 256 + tid;
        int c  = i4 >> 5;
        int h4 = i4 & 31;
        float4 t = *(const float4*)&Bs[c * 136 + h4 * 4];
        *((float4*)(gtile + (size_t)c * NPIX) + h4) = t;
    }
}

extern "C" void kernel_launch(void* const* d_in, const int* in_sizes, int n_in,
                              void* d_out, int out_size)
{
    (void)in_sizes; (void)n_in; (void)out_size;
    const float* x = (const float*)d_in[0];
    const float* v = (const float*)d_in[1];
    const float* T = (const float*)d_in[2];
    const float* W = (const float*)d_in[3];
    float* out = (float*)d_out;

    float* scratch = nullptr;
    cudaGetSymbolAddress((void**)&scratch, g_scratch);

    const int smem1 = 128 * 128 * 4;   // 65536 B
    cudaFuncSetAttribute(fwht2d_kernel, cudaFuncAttributeMaxDynamicSharedMemorySize, smem1);

    prep_kernel<<<4, 256>>>(W);
    fwht2d_kernel<<<NIMG, 256, smem1>>>(x, scratch, 1.0f, 1);
    podmix_kernel<<<B_ * 128, 256>>>(scratch, v, T);
    fwht2d_kernel<<<NIMG, 256, smem1>>>(scratch, out, 1.0f / 16384.0f, 0);
}

// round 15
// speedup vs baseline: 1.1239x; 1.0097x over previous
#include <cuda_runtime.h>
#include <cstdint>

#define B_    32
#define HW_   128
#define NPIX  16384
#define NIMG  2048

// 128MB scratch: f2 (tf32-rounded) transposed [b,c,w,h], then (f6+f2) in-place
__device__ float g_scratch[(size_t)B_ * 64 * NPIX];
// pre-converted tf32 weights in per-thread fragment order
__device__ float g_wtf[8192];

// XOR-swizzled smem layout for fwht, stride 128 words (no pad)
__device__ __forceinline__ int sidx(int r, int h) {
    return r * 128 + ((((h >> 2) ^ r) & 31) << 2) + (h & 3);
}
__device__ __forceinline__ int sidx4(int r, int h4) {
    return r * 128 + (((h4 ^ r) & 31) << 2);
}

__device__ __forceinline__ uint32_t f2tf(float x) {
    uint32_t r; asm("cvt.rna.tf32.f32 %0, %1;" : "=r"(r) : "f"(x)); return r;
}
__device__ __forceinline__ float softth(float x, float t) {
    float tt = fmaxf(t, 0.f);
    return copysignf(fmaxf(fabsf(x) - tt, 0.f), x);
}
__device__ __forceinline__ void mma_tf32(float* d, uint32_t a0, uint32_t a1, uint32_t a2, uint32_t a3,
                                         uint32_t b0, uint32_t b1) {
    asm volatile(
        "mma.sync.aligned.m16n8k8.row.col.f32.tf32.tf32.f32 "
        "{%0,%1,%2,%3}, {%4,%5,%6,%7}, {%8,%9}, {%0,%1,%2,%3};\n"
        : "+f"(d[0]), "+f"(d[1]), "+f"(d[2]), "+f"(d[3])
        : "r"(a0), "r"(a1), "r"(a2), "r"(a3), "r"(b0), "r"(b1));
}
__device__ __forceinline__ void cpa16(uint32_t d, const void* s) {
    asm volatile("cp.async.cg.shared.global [%0], [%1], 16;" :: "r"(d), "l"(s));
}
__device__ __forceinline__ void cpa_commit_wait() {
    asm volatile("cp.async.commit_group;" ::: "memory");
    asm volatile("cp.async.wait_group 0;" ::: "memory");
}

// ---------------------------------------------------------------------------
// prep: conv_w -> tf32, fragment-ordered for podmix mainloop
// ---------------------------------------------------------------------------
__global__ void prep_kernel(const float* __restrict__ W)
{
    int t = blockIdx.x * 256 + threadIdx.x;
    if (t >= 1024) return;
    int tig = t & 3, gid = (t >> 2) & 7, mq = (t >> 5) & 3, kb = t >> 7;
    int k0 = kb * 8 + tig;
    int r0 = mq * 16 + gid;
    float* o = g_wtf + t * 8;
    o[0] = __uint_as_float(f2tf(__ldg(W + r0 * 64 + k0)));
    o[1] = __uint_as_float(f2tf(__ldg(W + (r0 + 8) * 64 + k0)));
    o[2] = __uint_as_float(f2tf(__ldg(W + r0 * 64 + k0 + 4)));
    o[3] = __uint_as_float(f2tf(__ldg(W + (r0 + 8) * 64 + k0 + 4)));
    int r1 = r0 + 64;
    o[4] = __uint_as_float(f2tf(__ldg(W + r1 * 64 + k0)));
    o[5] = __uint_as_float(f2tf(__ldg(W + (r1 + 8) * 64 + k0)));
    o[6] = __uint_as_float(f2tf(__ldg(W + r1 * 64 + k0 + 4)));
    o[7] = __uint_as_float(f2tf(__ldg(W + (r1 + 8) * 64 + k0 + 4)));
}

// ---------------------------------------------------------------------------
// Pass 1 / Pass 3: 2D FWHT of 128x128 image, output TRANSPOSED, scaled.
// (Exact R5-proven structure: LDG+STS staging, 64 floats/thread, XOR swizzle.)
// ---------------------------------------------------------------------------
__global__ void __launch_bounds__(256, 2)
fwht2d_kernel(const float* __restrict__ in, float* __restrict__ out,
              float scale, int do_round)
{
    extern __shared__ float s[];
    const int img = blockIdx.x;
    const int tid = threadIdx.x;
    const float* gin  = in  + (size_t)img * NPIX;
    float*       gout = out + (size_t)img * NPIX;

    #pragma unroll
    for (int k = 0; k < 16; k++) {
        int gi = k * 256 + tid;
        int r  = gi >> 5;
        int c4 = gi & 31;
        float4 v4 = __ldg((const float4*)gin + gi);
        *(float4*)&s[sidx4(r, c4)] = v4;
    }
    __syncthreads();

    float reg[64];

    // phase W
    {
        int r = tid >> 1, half = tid & 1;
        #pragma unroll
        for (int j4 = 0; j4 < 16; j4++) {
            float4 a = *(const float4*)&s[sidx4(r, j4)];
            float4 b = *(const float4*)&s[sidx4(r, j4 + 16)];
            if (half) {
                reg[4*j4+0] = a.x - b.x; reg[4*j4+1] = a.y - b.y;
                reg[4*j4+2] = a.z - b.z; reg[4*j4+3] = a.w - b.w;
            } else {
                reg[4*j4+0] = a.x + b.x; reg[4*j4+1] = a.y + b.y;
                reg[4*j4+2] = a.z + b.z; reg[4*j4+3] = a.w + b.w;
            }
        }
        #pragma unroll
        for (int st = 1; st < 64; st <<= 1)
            #pragma unroll
            for (int i = 0; i < 64; i++)
                if ((i & st) == 0) {
                    float a = reg[i], b = reg[i + st];
                    reg[i] = a + b;  reg[i + st] = a - b;
                }
        __syncthreads();
        #pragma unroll
        for (int j4 = 0; j4 < 16; j4++)
            *(float4*)&s[sidx4(r, half * 16 + j4)] =
                make_float4(reg[4*j4], reg[4*j4+1], reg[4*j4+2], reg[4*j4+3]);
    }
    __syncthreads();

    // phase H (writes transposed)
    {
        int w = tid & 127, hh = tid >> 7;
        #pragma unroll
        for (int j = 0; j < 64; j++) {
            float a = s[sidx(j, w)];
            float b = s[sidx(j + 64, w)];
            reg[j] = hh ? (a - b) : (a + b);
        }
        #pragma unroll
        for (int st = 1; st < 64; st <<= 1)
            #pragma unroll
            for (int i = 0; i < 64; i++)
                if ((i & st) == 0) {
                    float a = reg[i], b = reg[i + st];
                    reg[i] = a + b;  reg[i + st] = a - b;
                }
        __syncthreads();
        #pragma unroll
        for (int j4 = 0; j4 < 16; j4++)
            *(float4*)&s[sidx4(w, hh * 16 + j4)] =
                make_float4(reg[4*j4], reg[4*j4+1], reg[4*j4+2], reg[4*j4+3]);
    }
    __syncthreads();

    if (do_round) {
        #pragma unroll
        for (int k = 0; k < 16; k++) {
            int gi = k * 256 + tid;
            int r  = gi >> 5;
            int c4 = gi & 31;
            float4 t = *(const float4*)&s[sidx4(r, c4)];
            ((float4*)gout)[gi] = make_float4(
                __uint_as_float(f2tf(t.x)), __uint_as_float(f2tf(t.y)),
                __uint_as_float(f2tf(t.z)), __uint_as_float(f2tf(t.w)));
        }
    } else {
        #pragma unroll
        for (int k = 0; k < 16; k++) {
            int gi = k * 256 + tid;
            int r  = gi >> 5;
            int c4 = gi & 31;
            float4 t = *(const float4*)&s[sidx4(r, c4)];
            ((float4*)gout)[gi] = make_float4(t.x*scale, t.y*scale, t.z*scale, t.w*scale);
        }
    }
}

// ---------------------------------------------------------------------------
// Pass 2: mma.sync tf32 per (b,w) tile (R14-proven: cp.async B staging).
// ---------------------------------------------------------------------------
__global__ void __launch_bounds__(256, 2)
podmix_kernel(float* __restrict__ f2, const float* __restrict__ v,
              const float* __restrict__ T)
{
    __shared__ float sm[9216];
    float*    Bs  = sm;               // [64 c][136 h] tf32 bits of f2 tile
    uint32_t* Bsu = (uint32_t*)sm;
    float*    vs0 = sm + 8704;
    float*    Ts0 = vs0 + 128;
    float*    vs1 = Ts0 + 128;
    float*    Ts1 = vs1 + 128;

    const int b    = blockIdx.x >> 7;
    const int w    = blockIdx.x & 127;
    const int tid  = threadIdx.x;
    const int wid  = tid >> 5;
    const int lane = tid & 31;
    const int gid  = lane >> 2;   // 0..7
    const int tig  = lane & 3;    // 0..3
    const int mq   = wid & 3;     // o-quarter (16 rows)
    const int nh   = wid >> 2;    // h half

    float* gtile = f2 + (((size_t)b * 64) * 128 + w) * 128;   // + c*NPIX + h

    // stage f2 tile (already tf32 bits) -> Bs via cp.async (pure copy)
    {
        uint32_t bsd = (uint32_t)__cvta_generic_to_shared(Bs);
        #pragma unroll
        for (int k = 0; k < 8; k++) {
            int i4 = k * 256 + tid;          // 2048 float4
            int c  = i4 >> 5;
            int h4 = i4 & 31;
            cpa16(bsd + (c * 136 + h4 * 4) * 4,
                  (const float4*)(gtile + (size_t)c * NPIX) + h4);
        }
    }
    // v/T columns for this w (regular loads, tiny; overlap the bulk copy)
    if (tid < 128) {
        vs0[tid] = __ldg(v + tid * 128 + w);
        Ts0[tid] = __ldg(T + tid * 128 + w);
    } else {
        int h = tid - 128;
        vs1[h] = __ldg(v + NPIX + h * 128 + w);
        Ts1[h] = __ldg(T + NPIX + h * 128 + w);
    }
    cpa_commit_wait();
    __syncthreads();

    float acc[16][4];
    #pragma unroll
    for (int i = 0; i < 16; i++) {
        acc[i][0] = 0.f; acc[i][1] = 0.f; acc[i][2] = 0.f; acc[i][3] = 0.f;
    }

    const float4* Aw = (const float4*)g_wtf;

    #pragma unroll
    for (int kb = 0; kb < 8; kb++) {
        int ai = (((kb * 4 + mq) * 8 + gid) * 4 + tig) * 2;
        float4 lo = __ldg(Aw + ai);
        float4 hi = __ldg(Aw + ai + 1);
        uint32_t a0 = __float_as_uint(lo.x), a1 = __float_as_uint(lo.y);
        uint32_t a2 = __float_as_uint(lo.z), a3 = __float_as_uint(lo.w);
        uint32_t a4 = __float_as_uint(hi.x), a5 = __float_as_uint(hi.y);
        uint32_t a6 = __float_as_uint(hi.z), a7 = __float_as_uint(hi.w);
        int r0 = (kb * 8 + tig) * 136 + nh * 64 + gid;
        int r1 = r0 + 4 * 136;
        #pragma unroll
        for (int nb = 0; nb < 8; nb++) {
            uint32_t b0 = Bsu[r0 + nb * 8];
            uint32_t b1 = Bsu[r1 + nb * 8];
            mma_tf32(acc[nb],     a0, a1, a2, a3, b0, b1);   // pod 0
            mma_tf32(acc[8 + nb], a4, a5, a6, a7, b0, b1);   // pod 1
        }
    }
    __syncthreads();   // all GEMM reads of Bs done

    // epilogue: combine pods in registers, add f2, write back into Bs
    {
        const int o = mq * 16 + gid;
        #pragma unroll
        for (int nb = 0; nb < 8; nb++) {
            int h = nh * 64 + nb * 8 + 2 * tig;
            float v0h = vs0[h], v0h1 = vs0[h+1], t0h = Ts0[h], t0h1 = Ts0[h+1];
            float v1h = vs1[h], v1h1 = vs1[h+1], t1h = Ts1[h], t1h1 = Ts1[h+1];
            float2 f0 = *(const float2*)&Bs[o * 136 + h];
            float2 f1 = *(const float2*)&Bs[(o + 8) * 136 + h];
            float2 r0 = make_float2(
                softth(v0h  * acc[nb][0], t0h)  + softth(v1h  * acc[8+nb][0], t1h)  + f0.x,
                softth(v0h1 * acc[nb][1], t0h1) + softth(v1h1 * acc[8+nb][1], t1h1) + f0.y);
            float2 r1 = make_float2(
                softth(v0h  * acc[nb][2], t0h)  + softth(v1h  * acc[8+nb][2], t1h)  + f1.x,
                softth(v0h1 * acc[nb][3], t0h1) + softth(v1h1 * acc[8+nb][3], t1h1) + f1.y);
            *(float2*)&Bs[o * 136 + h]       = r0;
            *(float2*)&Bs[(o + 8) * 136 + h] = r1;
        }
    }
    __syncthreads();

    // coalesced store back in place
    #pragma unroll
    for (int k = 0; k < 8; k++) {
        int i4 = k * 256 + tid;
        int c  = i4 >> 5;
        int h4 = i4 & 31;
        float4 t = *(const float4*)&Bs[c * 136 + h4 * 4];
        *((float4*)(gtile + (size_t)c * NPIX) + h4) = t;
    }
}

extern "C" void kernel_launch(void* const* d_in, const int* in_sizes, int n_in,
                              void* d_out, int out_size)
{
    (void)in_sizes; (void)n_in; (void)out_size;
    const float* x = (const float*)d_in[0];
    const float* v = (const float*)d_in[1];
    const float* T = (const float*)d_in[2];
    const float* W = (const float*)d_in[3];
    float* out = (float*)d_out;

    float* scratch = nullptr;
    cudaGetSymbolAddress((void**)&scratch, g_scratch);

    const int smem1 = 128 * 128 * 4;   // 65536 B
    cudaFuncSetAttribute(fwht2d_kernel, cudaFuncAttributeMaxDynamicSharedMemorySize, smem1);

    prep_kernel<<<4, 256>>>(W);
    fwht2d_kernel<<<NIMG, 256, smem1>>>(x, scratch, 1.0f, 1);
    podmix_kernel<<<B_ * 128, 256>>>(scratch, v, T);
    fwht2d_kernel<<<NIMG, 256, smem1>>>(scratch, out, 1.0f / 16384.0f, 0);
}